// round 1
// baseline (speedup 1.0000x reference)
#include <cuda_runtime.h>
#include <math.h>

// Problem constants
#define NB   8          // batches
#define NV   2048       // v per batch
#define NP   32         // points per patch
#define NSH  16         // spherical-harmonic count (l=0..3)
#define NS   4          // shells
#define NM   20         // monomials (deg <= 3 in 3 vars)

#define P1_BLOCKS   1024     // 16 v per block
#define P1B_THREADS 128
#define P2_BLOCKS   2048     // 256 points per block

// Scratch (fully overwritten every launch -> deterministic, no memset needed)
__device__ float g_partial[P1_BLOCKS * 16];   // per-block partial sums of sqrt terms, [block][l*4+s]
__device__ float g_invnorm[NB * 16];          // 1/ml, [b][l*4+s]

// monomials in lexicographic (i,j,k) order, exponents applied to (x,y,z)
__device__ __forceinline__ void eval_monoms(float x, float y, float z, float* m) {
    float z2 = z * z, z3 = z2 * z;
    float y2 = y * y, y3 = y2 * y;
    float x2 = x * x, x3 = x2 * x;
    float yz = y * z;
    m[0]  = 1.0f;   m[1]  = z;      m[2]  = z2;     m[3]  = z3;
    m[4]  = y;      m[5]  = yz;     m[6]  = y * z2; m[7]  = y2;
    m[8]  = y2 * z; m[9]  = y3;     m[10] = x;      m[11] = x * z;
    m[12] = x * z2; m[13] = x * y;  m[14] = x * yz; m[15] = x * y2;
    m[16] = x2;     m[17] = x2 * z; m[18] = x2 * y; m[19] = x3;
}

// normalized + masked gaussian shells
__device__ __forceinline__ void eval_shells(float dist, float* sw) {
    const float r1 = 1.0f / 3.0f, r2 = 2.0f / 3.0f;
    float d0 = dist, d1 = dist - r1, d2 = dist - r2, d3 = dist - 1.0f;
    float e0 = __expf(-16.0f * d0 * d0);
    float e1 = __expf(-16.0f * d1 * d1);
    float e2 = __expf(-16.0f * d2 * d2);
    float e3 = __expf(-16.0f * d3 * d3);
    float inv = 1.0f / fmaxf(e0 + e1 + e2 + e3, 1e-6f);
    if (dist > 1.0f) inv = 0.0f;   // where(dist<=1, shells, 0)
    sw[0] = e0 * inv; sw[1] = e1 * inv; sw[2] = e2 * inv; sw[3] = e3 * inv;
}

// -------------------------------------------------------------------------
// pass1: per-(b,v,l,s) accumulate A = sum_p shell_s^2 * sum_{i in l} sh_i^2,
//        then per-block partial of sum_v sqrt(A). Deterministic.
// Layout: block = 256 threads = 8 warps = 16 v (half-warp per v),
//         lane%16 = SH index i (Y row held in registers).
// -------------------------------------------------------------------------
__global__ __launch_bounds__(256) void sh_pass1(
    const float* __restrict__ patches, const float* __restrict__ Y)
{
    __shared__ float red[8][32][4];    // [warp][lane][s]
    __shared__ float red2[16][16];     // [v_local][l*4+s]

    int tid  = threadIdx.x;
    int warp = tid >> 5, lane = tid & 31;
    int hw   = lane >> 4, li = lane & 15;          // half-warp (which v), SH index
    int gv   = blockIdx.x * 16 + warp * 2 + hw;    // global (b*NV+v)

    float Yr[NM];
#pragma unroll
    for (int j = 0; j < NM; j++) Yr[j] = __ldg(Y + li * NM + j);

    float acc0 = 0.f, acc1 = 0.f, acc2 = 0.f, acc3 = 0.f;
    const float* pbase = patches + (size_t)gv * NP * 3;

#pragma unroll 4
    for (int p = 0; p < NP; p++) {
        float x = __ldg(pbase + p * 3 + 0);
        float y = __ldg(pbase + p * 3 + 1);
        float z = __ldg(pbase + p * 3 + 2);
        float dist = sqrtf(x * x + y * y + z * z);
        float invd = -1.0f / fmaxf(dist, 1e-6f);   // negation folded in
        float m[NM];
        eval_monoms(x * invd, y * invd, z * invd, m);
        float s = 0.f;
#pragma unroll
        for (int j = 0; j < NM; j++) s = fmaf(Yr[j], m[j], s);
        float sw[4];
        eval_shells(dist, sw);
        float s2 = s * s;
        acc0 = fmaf(sw[0] * sw[0], s2, acc0);
        acc1 = fmaf(sw[1] * sw[1], s2, acc1);
        acc2 = fmaf(sw[2] * sw[2], s2, acc2);
        acc3 = fmaf(sw[3] * sw[3], s2, acc3);
    }

    red[warp][lane][0] = acc0;
    red[warp][lane][1] = acc1;
    red[warp][lane][2] = acc2;
    red[warp][lane][3] = acc3;
    __syncthreads();

    // stage B: thread t -> (v_local, l, s); sum lanes belonging to degree l, sqrt.
    {
        int vl = tid >> 4, ls = tid & 15;
        int l = ls >> 2, s = ls & 3;
        int w = vl >> 1, lb = (vl & 1) * 16;
        int lo, hi;
        if      (l == 0) { lo = 0;  hi = 0;  }
        else if (l == 1) { lo = 1;  hi = 3;  }
        else if (l == 2) { lo = 4;  hi = 8;  }
        else             { lo = 9;  hi = 15; }
        float sum = 0.f;
        for (int q = lo; q <= hi; q++) sum += red[w][lb + q][s];
        red2[vl][ls] = sqrtf(sum);
    }
    __syncthreads();

    // stage C: sum over the block's 16 v's -> one partial per (l,s)
    if (tid < 16) {
        float t = 0.f;
#pragma unroll
        for (int vv = 0; vv < 16; vv++) t += red2[vv][tid];
        g_partial[blockIdx.x * 16 + tid] = t;
    }
}

// -------------------------------------------------------------------------
// pass1b: reduce 128 block-partials per batch -> invnorm[b][l][s]
// -------------------------------------------------------------------------
__global__ void sh_pass1b() {
    int t  = threadIdx.x;          // 128 threads: 8 b x 16 (l,s)
    int b  = t >> 4, ls = t & 15;
    float sum = 0.f;
    const int blocks_per_b = P1_BLOCKS / NB;   // 128
    for (int c = 0; c < blocks_per_b; c++)
        sum += g_partial[(b * blocks_per_b + c) * 16 + ls];
    float ml = fmaxf(sum * (1.0f / (float)NV), 1e-8f);
    g_invnorm[b * 16 + ls] = 1.0f / ml;
}

// -------------------------------------------------------------------------
// pass2: thread = (point, i). 16 threads per point, each writes float4 (s=0..3)
//        -> fully coalesced 512B per warp. Y row + invnorm cached in registers
//        across 16 point-iterations per thread.
// -------------------------------------------------------------------------
__global__ __launch_bounds__(256) void sh_pass2(
    const float* __restrict__ patches, const float* __restrict__ Y,
    float* __restrict__ out)
{
    int tid = threadIdx.x;
    int i   = tid & 15;           // SH index
    int gl  = tid >> 4;           // point-group within block (0..15)
    int l   = (i == 0) ? 0 : (i < 4) ? 1 : (i < 9) ? 2 : 3;
    int b   = blockIdx.x >> 8;    // 256 blocks per batch

    float Yr[NM];
#pragma unroll
    for (int j = 0; j < NM; j++) Yr[j] = __ldg(Y + i * NM + j);

    float4 invn = *reinterpret_cast<const float4*>(&g_invnorm[b * 16 + l * 4]);

    int pt_block = blockIdx.x * 256;   // 256 points per block

#pragma unroll 4
    for (int k = 0; k < 16; k++) {
        int pt = pt_block + k * 16 + gl;
        const float* pp = patches + (size_t)pt * 3;
        float x = __ldg(pp + 0);
        float y = __ldg(pp + 1);
        float z = __ldg(pp + 2);
        float dist = sqrtf(x * x + y * y + z * z);
        float invd = -1.0f / fmaxf(dist, 1e-6f);
        float m[NM];
        eval_monoms(x * invd, y * invd, z * invd, m);
        float s = 0.f;
#pragma unroll
        for (int j = 0; j < NM; j++) s = fmaf(Yr[j], m[j], s);
        float sw[4];
        eval_shells(dist, sw);
        float4 o;
        o.x = sw[0] * s * invn.x;
        o.y = sw[1] * s * invn.y;
        o.z = sw[2] * s * invn.z;
        o.w = sw[3] * s * invn.w;
        reinterpret_cast<float4*>(out)[(size_t)pt * 16 + i] = o;
    }
}

extern "C" void kernel_launch(void* const* d_in, const int* in_sizes, int n_in,
                              void* d_out, int out_size) {
    const float* patches = (const float*)d_in[0];   // (8,2048,32,3)
    const float* Y       = (const float*)d_in[1];   // (16,20)
    float* out           = (float*)d_out;           // (8,2048,32,16,4)
    (void)in_sizes; (void)n_in; (void)out_size;

    sh_pass1 <<<P1_BLOCKS, 256>>>(patches, Y);
    sh_pass1b<<<1, P1B_THREADS>>>();
    sh_pass2 <<<P2_BLOCKS, 256>>>(patches, Y, out);
}

// round 2
// speedup vs baseline: 1.3968x; 1.3968x over previous
#include <cuda_runtime.h>
#include <math.h>

typedef unsigned long long u64;

#define NB   8
#define NV   2048
#define NP   32
#define NM   20

#define P1_BLOCKS 1024     // 16 v per block
#define P2_BLOCKS 1024     // 256 point-pairs per block

// Scratch (fully overwritten every launch -> deterministic)
__device__ float g_partial[P1_BLOCKS * 16];
__device__ float g_invnorm[NB * 16];

// ---------------- packed f32x2 helpers (Blackwell) ----------------
__device__ __forceinline__ u64 pk2(float lo, float hi) {
    u64 r; asm("mov.b64 %0, {%1,%2};" : "=l"(r) : "f"(lo), "f"(hi)); return r;
}
__device__ __forceinline__ void up2(u64 v, float& lo, float& hi) {
    asm("mov.b64 {%0,%1}, %2;" : "=f"(lo), "=f"(hi) : "l"(v));
}
__device__ __forceinline__ u64 fma2(u64 a, u64 b, u64 c) {
    u64 d; asm("fma.rn.f32x2 %0,%1,%2,%3;" : "=l"(d) : "l"(a), "l"(b), "l"(c)); return d;
}
__device__ __forceinline__ u64 mul2(u64 a, u64 b) {
    u64 d; asm("mul.rn.f32x2 %0,%1,%2;" : "=l"(d) : "l"(a), "l"(b)); return d;
}
__device__ __forceinline__ u64 add2(u64 a, u64 b) {
    u64 d; asm("add.rn.f32x2 %0,%1,%2;" : "=l"(d) : "l"(a), "l"(b)); return d;
}
__device__ __forceinline__ float ex2a(float x) {
    float r; asm("ex2.approx.f32 %0, %1;" : "=f"(r) : "f"(x)); return r;
}
__device__ __forceinline__ float rcpa(float x) {
    float r; asm("rcp.approx.f32 %0, %1;" : "=f"(r) : "f"(x)); return r;
}

// shell constants: f_k = exp(32 r_k d - 16 r_k^2), r_k = k/3
// f1 = 2^(A1*d + B1); f2 = (C1*f1)^2; f3 = C2*f1*f2
#define SH_A1  15.3887470903f     // (32/3)*log2(e)
#define SH_B1  -2.5647911817f     // -(16/9)*log2(e)
#define SH_C1   0.1690133154f     // exp(-16/9)
#define SH_C2   8.1598804e-4f     // exp(-64/9)

// Shared per-pair math: given packed coords (2 points), packed Y row, produce
// packed g = s*inv (shell-normalized, masked) and f1,f2,f3.
#define PAIR_MATH(Q0, Q1, Q2)                                                    \
    u64 ux = pk2((Q0).x, (Q1).y), uy = pk2((Q0).y, (Q2).x), uz = pk2((Q1).x, (Q2).y); \
    u64 r2 = fma2(ux, ux, fma2(uy, uy, mul2(uz, uz)));                           \
    float r2a, r2b; up2(r2, r2a, r2b);                                           \
    float da = sqrtf(r2a), db = sqrtf(r2b);                                      \
    float ia = rcpa(fmaxf(da, 1e-6f)), ib = rcpa(fmaxf(db, 1e-6f));              \
    u64 uinv = pk2(-ia, -ib);                                                    \
    u64 nx = mul2(ux, uinv), ny = mul2(uy, uinv), nz = mul2(uz, uinv);           \
    u64 pA = fma2(nz, fma2(nz, fma2(nz, Yp[3], Yp[2]), Yp[1]), Yp[0]);           \
    u64 pB = fma2(nz, fma2(nz, Yp[6], Yp[5]), Yp[4]);                            \
    u64 pC = fma2(nz, Yp[8], Yp[7]);                                             \
    u64 pD = fma2(nz, fma2(nz, Yp[12], Yp[11]), Yp[10]);                         \
    u64 pE = fma2(nz, Yp[14], Yp[13]);                                           \
    u64 pF = fma2(nz, Yp[17], Yp[16]);                                           \
    u64 pG = fma2(nx, Yp[19], fma2(ny, Yp[18], pF));                             \
    u64 pH = fma2(ny, Yp[15], pE);                                               \
    u64 pX = fma2(nx, pG, fma2(ny, pH, pD));                                     \
    u64 pT = fma2(ny, fma2(ny, fma2(ny, Yp[9], pC), pB), pA);                    \
    u64 s  = fma2(nx, pX, pT);                                                   \
    u64 uds = pk2(fminf(da, 1.0f), fminf(db, 1.0f));                             \
    u64 ea = fma2(uds, KA1, KB1);                                                \
    float eaa, eab; up2(ea, eaa, eab);                                           \
    u64 f1 = pk2(ex2a(eaa), ex2a(eab));                                          \
    u64 ft = mul2(f1, KC1);                                                      \
    u64 f2 = mul2(ft, ft);                                                       \
    u64 f3 = mul2(mul2(f1, f2), KC2);                                            \
    u64 fsum = add2(add2(f1, f2), add2(f3, KONE));                               \
    float sa, sb; up2(fsum, sa, sb);                                             \
    float wa = (da <= 1.0f) ? rcpa(sa) : 0.0f;                                   \
    float wb = (db <= 1.0f) ? rcpa(sb) : 0.0f;                                   \
    u64 g  = mul2(s, pk2(wa, wb));                                               \
    u64 h1 = mul2(f1, g), h2 = mul2(f2, g), h3 = mul2(f3, g);

// -------------------------------------------------------------------------
// pass1: per (b,v,l,s) accumulate sum_p shell_s^2 * sum_{i in l} sh_i^2,
//        reduce to per-block partial of sum_v sqrt(.). Deterministic.
// warp = 2 v (half-warp each); lane&15 = SH row i; 2 packed points / iter.
// -------------------------------------------------------------------------
__global__ __launch_bounds__(256) void sh_pass1(
    const float* __restrict__ patches, const float* __restrict__ Y)
{
    __shared__ float red[8][32][4];
    __shared__ float red2[16][16];

    int tid  = threadIdx.x;
    int warp = tid >> 5, lane = tid & 31;
    int hw   = lane >> 4, li = lane & 15;
    int gv   = blockIdx.x * 16 + warp * 2 + hw;

    u64 Yp[NM];
#pragma unroll
    for (int j = 0; j < NM; j++) { float yv = __ldg(Y + li * NM + j); Yp[j] = pk2(yv, yv); }

    const u64 KA1 = pk2(SH_A1, SH_A1), KB1 = pk2(SH_B1, SH_B1);
    const u64 KC1 = pk2(SH_C1, SH_C1), KC2 = pk2(SH_C2, SH_C2);
    const u64 KONE = pk2(1.0f, 1.0f);

    u64 acc0 = 0ULL, acc1 = 0ULL, acc2 = 0ULL, acc3 = 0ULL;
    const float2* pb = (const float2*)(patches + (size_t)gv * (NP * 3));

#pragma unroll 4
    for (int k = 0; k < 16; k++) {
        float2 q0 = __ldg(pb + 3 * k + 0);
        float2 q1 = __ldg(pb + 3 * k + 1);
        float2 q2 = __ldg(pb + 3 * k + 2);
        PAIR_MATH(q0, q1, q2)
        acc0 = fma2(g,  g,  acc0);
        acc1 = fma2(h1, h1, acc1);
        acc2 = fma2(h2, h2, acc2);
        acc3 = fma2(h3, h3, acc3);
    }

    float x0a,x0b,x1a,x1b,x2a,x2b,x3a,x3b;
    up2(acc0,x0a,x0b); up2(acc1,x1a,x1b); up2(acc2,x2a,x2b); up2(acc3,x3a,x3b);
    red[warp][lane][0] = x0a + x0b;
    red[warp][lane][1] = x1a + x1b;
    red[warp][lane][2] = x2a + x2b;
    red[warp][lane][3] = x3a + x3b;
    __syncthreads();

    // stage B: thread t -> (v_local, l, s); sum lanes of degree l, sqrt.
    {
        int vl = tid >> 4, ls = tid & 15;
        int l = ls >> 2, sdx = ls & 3;
        int w = vl >> 1, lb = (vl & 1) * 16;
        int lo, hi;
        if      (l == 0) { lo = 0; hi = 0;  }
        else if (l == 1) { lo = 1; hi = 3;  }
        else if (l == 2) { lo = 4; hi = 8;  }
        else             { lo = 9; hi = 15; }
        float sum = 0.f;
        for (int q = lo; q <= hi; q++) sum += red[w][lb + q][sdx];
        red2[vl][ls] = sqrtf(sum);
    }
    __syncthreads();

    if (tid < 16) {
        float t = 0.f;
#pragma unroll
        for (int vv = 0; vv < 16; vv++) t += red2[vv][tid];
        g_partial[blockIdx.x * 16 + tid] = t;
    }
}

// -------------------------------------------------------------------------
// pass1b: reduce 128 block-partials per batch -> invnorm[b][l][s]
// -------------------------------------------------------------------------
__global__ void sh_pass1b() {
    int t  = threadIdx.x;          // 128 threads: 8 b x 16 (l,s)
    int b  = t >> 4, ls = t & 15;
    float sum = 0.f;
    const int blocks_per_b = P1_BLOCKS / NB;   // 128
    for (int c = 0; c < blocks_per_b; c++)
        sum += g_partial[(b * blocks_per_b + c) * 16 + ls];
    float ml = fmaxf(sum * (1.0f / (float)NV), 1e-8f);
    g_invnorm[b * 16 + ls] = 1.0f / ml;
}

// -------------------------------------------------------------------------
// pass2: lane = (point-pair stream gl, SH row i). 2 packed points per iter,
//        2x STG.128 coalesced output. invnorm + Y row in registers.
// -------------------------------------------------------------------------
__global__ __launch_bounds__(256) void sh_pass2(
    const float* __restrict__ patches, const float* __restrict__ Y,
    float* __restrict__ out)
{
    int tid = threadIdx.x;
    int i   = tid & 15;          // SH index
    int gl  = tid >> 4;          // pair-stream within block (0..15)
    int l   = (i == 0) ? 0 : (i < 4) ? 1 : (i < 9) ? 2 : 3;
    int b   = blockIdx.x >> 7;   // 128 blocks per batch

    u64 Yp[NM];
#pragma unroll
    for (int j = 0; j < NM; j++) { float yv = __ldg(Y + i * NM + j); Yp[j] = pk2(yv, yv); }

    const u64 KA1 = pk2(SH_A1, SH_A1), KB1 = pk2(SH_B1, SH_B1);
    const u64 KC1 = pk2(SH_C1, SH_C1), KC2 = pk2(SH_C2, SH_C2);
    const u64 KONE = pk2(1.0f, 1.0f);

    float4 inq = *reinterpret_cast<const float4*>(&g_invnorm[b * 16 + l * 4]);
    u64 I0 = pk2(inq.x, inq.x), I1 = pk2(inq.y, inq.y);
    u64 I2 = pk2(inq.z, inq.z), I3 = pk2(inq.w, inq.w);

    int pairBase = blockIdx.x * 256;     // 256 point-pairs per block
    float4* o4 = (float4*)out;

#pragma unroll 4
    for (int k = 0; k < 16; k++) {
        int pr = pairBase + k * 16 + gl;
        const float2* q = (const float2*)(patches) + 3 * (size_t)pr;
        float2 q0 = __ldg(q + 0);
        float2 q1 = __ldg(q + 1);
        float2 q2 = __ldg(q + 2);
        PAIR_MATH(q0, q1, q2)
        u64 o0 = mul2(g,  I0);
        u64 o1 = mul2(h1, I1);
        u64 o2 = mul2(h2, I2);
        u64 o3 = mul2(h3, I3);
        float o0a,o0b,o1a,o1b,o2a,o2b,o3a,o3b;
        up2(o0,o0a,o0b); up2(o1,o1a,o1b); up2(o2,o2a,o2b); up2(o3,o3a,o3b);
        size_t idx = (size_t)pr * 32 + i;      // 2 points x 16 float4 per pair
        o4[idx]      = make_float4(o0a, o1a, o2a, o3a);
        o4[idx + 16] = make_float4(o0b, o1b, o2b, o3b);
    }
}

extern "C" void kernel_launch(void* const* d_in, const int* in_sizes, int n_in,
                              void* d_out, int out_size) {
    const float* patches = (const float*)d_in[0];   // (8,2048,32,3)
    const float* Y       = (const float*)d_in[1];   // (16,20)
    float* out           = (float*)d_out;           // (8,2048,32,16,4)
    (void)in_sizes; (void)n_in; (void)out_size;

    sh_pass1 <<<P1_BLOCKS, 256>>>(patches, Y);
    sh_pass1b<<<1, 128>>>();
    sh_pass2 <<<P2_BLOCKS, 256>>>(patches, Y, out);
}

// round 3
// speedup vs baseline: 1.6307x; 1.1675x over previous
#include <cuda_runtime.h>
#include <math.h>

typedef unsigned long long u64;

#define NB   8
#define NV   2048
#define NP   32
#define NM   20
#define NPAIRS (NB * NV * NP / 2)     // 131072 point-pairs

#define P1_BLOCKS 1024     // 16 v per block
#define P2_BLOCKS 1024     // 256 point-pairs per block

// Scratch (fully overwritten every launch -> deterministic)
__device__ float g_geom[NPAIRS * 16];        // 8 MB: per-pair packed geometry record
__device__ float g_partial[P1_BLOCKS * 16];
__device__ float g_invnorm[NB * 16];

// ---------------- packed f32x2 helpers (Blackwell) ----------------
__device__ __forceinline__ u64 pk2(float lo, float hi) {
    u64 r; asm("mov.b64 %0, {%1,%2};" : "=l"(r) : "f"(lo), "f"(hi)); return r;
}
__device__ __forceinline__ void up2(u64 v, float& lo, float& hi) {
    asm("mov.b64 {%0,%1}, %2;" : "=f"(lo), "=f"(hi) : "l"(v));
}
__device__ __forceinline__ u64 fma2(u64 a, u64 b, u64 c) {
    u64 d; asm("fma.rn.f32x2 %0,%1,%2,%3;" : "=l"(d) : "l"(a), "l"(b), "l"(c)); return d;
}
__device__ __forceinline__ u64 mul2(u64 a, u64 b) {
    u64 d; asm("mul.rn.f32x2 %0,%1,%2;" : "=l"(d) : "l"(a), "l"(b)); return d;
}
__device__ __forceinline__ float ex2a(float x) {
    float r; asm("ex2.approx.f32 %0, %1;" : "=f"(r) : "f"(x)); return r;
}
__device__ __forceinline__ float rcpa(float x) {
    float r; asm("rcp.approx.f32 %0, %1;" : "=f"(r) : "f"(x)); return r;
}
__device__ __forceinline__ float rsqa(float x) {
    float r; asm("rsqrt.approx.f32 %0, %1;" : "=f"(r) : "f"(x)); return r;
}

// shell constants: f_k = exp(32 r_k d - 16 r_k^2), r_k = k/3
// f1 = 2^(A1*d + B1); f2 = (C1*f1)^2; f3 = C2*f1*f2   (f0 = 1)
#define SH_A1  15.3887470903f     // (32/3)*log2(e)
#define SH_B1  -2.5647911817f     // -(16/9)*log2(e)
#define SH_C1   0.1690133154f     // exp(-16/9)
#define SH_C2   8.1598804e-4f     // exp(-64/9)

// Horner-factored evaluation of s = sum_j Y_j * m_j (19 packed FMA).
// Same factorization as the R2 kernel that passed (rel_err 2.6e-7).
#define POLY_S(nx, ny, nz, s)                                                  \
    u64 pA = fma2(nz, fma2(nz, fma2(nz, Yp[3], Yp[2]), Yp[1]), Yp[0]);         \
    u64 pB = fma2(nz, fma2(nz, Yp[6], Yp[5]), Yp[4]);                          \
    u64 pC = fma2(nz, Yp[8], Yp[7]);                                           \
    u64 pD = fma2(nz, fma2(nz, Yp[12], Yp[11]), Yp[10]);                       \
    u64 pE = fma2(nz, Yp[14], Yp[13]);                                         \
    u64 pF = fma2(nz, Yp[17], Yp[16]);                                         \
    u64 pG = fma2(nx, Yp[19], fma2(ny, Yp[18], pF));                           \
    u64 pH = fma2(ny, Yp[15], pE);                                             \
    u64 pX = fma2(nx, pG, fma2(ny, pH, pD));                                   \
    u64 pT = fma2(ny, fma2(ny, fma2(ny, Yp[9], pC), pB), pA);                  \
    u64 s  = fma2(nx, pX, pT);

// -------------------------------------------------------------------------
// prep: per point compute geometry once. Record per pair (16 floats, 64B):
//   [nxA,nxB, nyA,nyB, nzA,nzB, sw0A,sw0B, sw1A,sw1B, sw2A,sw2B, sw3A,sw3B, 0,0]
// i.e. as u64 fields: nx, ny, nz, sw0, sw1, sw2, sw3, pad  (ready for f32x2)
// -------------------------------------------------------------------------
__device__ __forceinline__ void geom1(float x, float y, float z,
                                      float& nx, float& ny, float& nz,
                                      float& s0, float& s1, float& s2, float& s3)
{
    float r2 = fmaf(x, x, fmaf(y, y, z * z));
    float r2c = fmaxf(r2, 1e-12f);
    float rinv = rsqa(r2c);
    float d = r2c * rinv;                 // == sqrt(r2)
    nx = -x * rinv; ny = -y * rinv; nz = -z * rinv;
    float de = fminf(d, 1.0f);
    float f1 = ex2a(fmaf(de, SH_A1, SH_B1));
    float ft = f1 * SH_C1;
    float f2 = ft * ft;
    float f3 = f1 * f2 * SH_C2;
    float sum = 1.0f + f1 + f2 + f3;      // f0 == 1, so sum >= 1 (clamp inert)
    float w = (r2 <= 1.0f) ? rcpa(sum) : 0.0f;   // exact mask via r2
    s0 = w; s1 = f1 * w; s2 = f2 * w; s3 = f3 * w;
}

__global__ __launch_bounds__(256) void sh_prep(const float* __restrict__ patches)
{
    int pr = blockIdx.x * 256 + threadIdx.x;      // pair id
    const float2* q = (const float2*)patches + 3 * (size_t)pr;
    float2 q0 = __ldg(q + 0), q1 = __ldg(q + 1), q2 = __ldg(q + 2);
    // point A = (q0.x, q0.y, q1.x), point B = (q1.y, q2.x, q2.y)
    float nxA, nyA, nzA, a0, a1, a2, a3;
    float nxB, nyB, nzB, b0, b1, b2, b3;
    geom1(q0.x, q0.y, q1.x, nxA, nyA, nzA, a0, a1, a2, a3);
    geom1(q1.y, q2.x, q2.y, nxB, nyB, nzB, b0, b1, b2, b3);
    float4* rec = (float4*)(g_geom + (size_t)pr * 16);
    rec[0] = make_float4(nxA, nxB, nyA, nyB);
    rec[1] = make_float4(nzA, nzB, a0, b0);
    rec[2] = make_float4(a1, b1, a2, b2);
    rec[3] = make_float4(a3, b3, 0.0f, 0.0f);
}

// -------------------------------------------------------------------------
// pass1: per (b,v,l,s) accumulate sum_p (shell_s*sh_i)^2 summed over i in l,
//        reduce to per-block partial of sum_v sqrt(.). Deterministic.
// warp = 2 v (half-warp each); lane&15 = SH row i; geometry loaded (broadcast).
// -------------------------------------------------------------------------
__global__ __launch_bounds__(256) void sh_pass1(const float* __restrict__ Y)
{
    __shared__ float red[8][32][4];
    __shared__ float red2[16][16];

    int tid  = threadIdx.x;
    int warp = tid >> 5, lane = tid & 31;
    int hw   = lane >> 4, li = lane & 15;
    int gv   = blockIdx.x * 16 + warp * 2 + hw;

    u64 Yp[NM];
#pragma unroll
    for (int j = 0; j < NM; j++) { float yv = __ldg(Y + li * NM + j); Yp[j] = pk2(yv, yv); }

    u64 acc0 = 0ULL, acc1 = 0ULL, acc2 = 0ULL, acc3 = 0ULL;
    const ulonglong2* gb = (const ulonglong2*)(g_geom + (size_t)gv * 16 * 16);

#pragma unroll
    for (int k = 0; k < 16; k++) {
        ulonglong2 r0 = __ldg(gb + 4 * k + 0);
        ulonglong2 r1 = __ldg(gb + 4 * k + 1);
        ulonglong2 r2 = __ldg(gb + 4 * k + 2);
        ulonglong2 r3 = __ldg(gb + 4 * k + 3);
        u64 nx = r0.x, ny = r0.y, nz = r1.x;
        u64 sw0 = r1.y, sw1 = r2.x, sw2 = r2.y, sw3 = r3.x;
        POLY_S(nx, ny, nz, s)
        u64 t0 = mul2(sw0, s); acc0 = fma2(t0, t0, acc0);
        u64 t1 = mul2(sw1, s); acc1 = fma2(t1, t1, acc1);
        u64 t2 = mul2(sw2, s); acc2 = fma2(t2, t2, acc2);
        u64 t3 = mul2(sw3, s); acc3 = fma2(t3, t3, acc3);
    }

    float x0a,x0b,x1a,x1b,x2a,x2b,x3a,x3b;
    up2(acc0,x0a,x0b); up2(acc1,x1a,x1b); up2(acc2,x2a,x2b); up2(acc3,x3a,x3b);
    red[warp][lane][0] = x0a + x0b;
    red[warp][lane][1] = x1a + x1b;
    red[warp][lane][2] = x2a + x2b;
    red[warp][lane][3] = x3a + x3b;
    __syncthreads();

    // stage B: thread t -> (v_local, l, s); sum lanes of degree l, sqrt.
    {
        int vl = tid >> 4, ls = tid & 15;
        int l = ls >> 2, sdx = ls & 3;
        int w = vl >> 1, lb = (vl & 1) * 16;
        int lo, hi;
        if      (l == 0) { lo = 0; hi = 0;  }
        else if (l == 1) { lo = 1; hi = 3;  }
        else if (l == 2) { lo = 4; hi = 8;  }
        else             { lo = 9; hi = 15; }
        float sum = 0.f;
        for (int qq = lo; qq <= hi; qq++) sum += red[w][lb + qq][sdx];
        red2[vl][ls] = sqrtf(sum);
    }
    __syncthreads();

    if (tid < 16) {
        float t = 0.f;
#pragma unroll
        for (int vv = 0; vv < 16; vv++) t += red2[vv][tid];
        g_partial[blockIdx.x * 16 + tid] = t;
    }
}

// -------------------------------------------------------------------------
// pass1b: reduce 128 block-partials per batch -> invnorm[b][l][s]
// -------------------------------------------------------------------------
__global__ void sh_pass1b() {
    int t  = threadIdx.x;          // 128 threads: 8 b x 16 (l,s)
    int b  = t >> 4, ls = t & 15;
    float sum = 0.f;
    const int blocks_per_b = P1_BLOCKS / NB;   // 128
    for (int c = 0; c < blocks_per_b; c++)
        sum += g_partial[(b * blocks_per_b + c) * 16 + ls];
    float ml = fmaxf(sum * (1.0f / (float)NV), 1e-8f);
    g_invnorm[b * 16 + ls] = 1.0f / ml;
}

// -------------------------------------------------------------------------
// pass2: lane = (pair-stream gl, SH row i). Geometry loaded pre-packed,
//        poly + 8 muls + 2 coalesced STG.128 per pair.
// -------------------------------------------------------------------------
__global__ __launch_bounds__(256) void sh_pass2(
    const float* __restrict__ Y, float* __restrict__ out)
{
    int tid = threadIdx.x;
    int i   = tid & 15;          // SH index
    int gl  = tid >> 4;          // pair-stream within block (0..15)
    int l   = (i == 0) ? 0 : (i < 4) ? 1 : (i < 9) ? 2 : 3;
    int b   = blockIdx.x >> 7;   // 128 blocks per batch

    u64 Yp[NM];
#pragma unroll
    for (int j = 0; j < NM; j++) { float yv = __ldg(Y + i * NM + j); Yp[j] = pk2(yv, yv); }

    float4 inq = *reinterpret_cast<const float4*>(&g_invnorm[b * 16 + l * 4]);
    u64 I0 = pk2(inq.x, inq.x), I1 = pk2(inq.y, inq.y);
    u64 I2 = pk2(inq.z, inq.z), I3 = pk2(inq.w, inq.w);

    int pairBase = blockIdx.x * 256;     // 256 point-pairs per block
    float4* o4 = (float4*)out;

#pragma unroll 4
    for (int k = 0; k < 16; k++) {
        int pr = pairBase + k * 16 + gl;
        const ulonglong2* gb = (const ulonglong2*)(g_geom + (size_t)pr * 16);
        ulonglong2 r0 = __ldg(gb + 0);
        ulonglong2 r1 = __ldg(gb + 1);
        ulonglong2 r2 = __ldg(gb + 2);
        ulonglong2 r3 = __ldg(gb + 3);
        u64 nx = r0.x, ny = r0.y, nz = r1.x;
        u64 sw0 = r1.y, sw1 = r2.x, sw2 = r2.y, sw3 = r3.x;
        POLY_S(nx, ny, nz, s)
        u64 o0 = mul2(mul2(sw0, s), I0);
        u64 o1 = mul2(mul2(sw1, s), I1);
        u64 o2 = mul2(mul2(sw2, s), I2);
        u64 o3 = mul2(mul2(sw3, s), I3);
        float o0a,o0b,o1a,o1b,o2a,o2b,o3a,o3b;
        up2(o0,o0a,o0b); up2(o1,o1a,o1b); up2(o2,o2a,o2b); up2(o3,o3a,o3b);
        size_t idx = (size_t)pr * 32 + i;      // 2 points x 16 float4 per pair
        o4[idx]      = make_float4(o0a, o1a, o2a, o3a);
        o4[idx + 16] = make_float4(o0b, o1b, o2b, o3b);
    }
}

extern "C" void kernel_launch(void* const* d_in, const int* in_sizes, int n_in,
                              void* d_out, int out_size) {
    const float* patches = (const float*)d_in[0];   // (8,2048,32,3)
    const float* Y       = (const float*)d_in[1];   // (16,20)
    float* out           = (float*)d_out;           // (8,2048,32,16,4)
    (void)in_sizes; (void)n_in; (void)out_size;

    sh_prep  <<<NPAIRS / 256, 256>>>(patches);
    sh_pass1 <<<P1_BLOCKS, 256>>>(Y);
    sh_pass1b<<<1, 128>>>();
    sh_pass2 <<<P2_BLOCKS, 256>>>(Y, out);
}